// round 16
// baseline (speedup 1.0000x reference)
#include <cuda_runtime.h>
#include <cstdint>

#define BB 16
#define DD 512
#define TT 2048
#define SS 2048      // padded s dimension (valid s < 2047)
#define SVALID 2047
#define LDA 136      // smem row stride (floats)
#define NSTG 3       // cp.async pipeline stages
#define BK 32        // k per chunk
#define NCHUNK 16    // DD / BK
#define TILE_FLOATS (BK * LDA)
#define SMEM_DYN (2 * NSTG * TILE_FLOATS * 4)   // 104448 B

// ---------------- scratch -----------------------------------------------------
__device__ float g_Xm[(size_t)BB * DD * TT];     // tf32 xs, [b][d][pi(s)]   (K1 A)
__device__ float g_Xn[(size_t)BB * DD * TT];     // tf32 xs, [b][d][sig(t)]  (K2 B)
__device__ float g_Wn[DD * DD];                  // tf32 W_KQ, [k][sig(d)]   (K1 B)
__device__ float g_Qt[(size_t)BB * DD * SS];     // tf32 q-tilde, [b][d][pi(s)] (K2 A)
__device__ float g_gpart[(size_t)BB * 16 * SS];
__device__ float g_g0[(size_t)BB * SS];
__device__ float g_y[BB * DD];
__device__ float g_r[BB * DD];
__device__ float g_wsum;

// ---------------- helpers ----------------------------------------------------
__device__ __forceinline__ float to_tf32(float x) {
    uint32_t u;
    asm("cvt.rna.tf32.f32 %0, %1;" : "=r"(u) : "f"(x));
    return __uint_as_float(u);
}
__device__ __forceinline__ uint32_t smem_u32(const void* p) {
    uint32_t a;
    asm("{ .reg .u64 t; cvta.to.shared.u64 t, %1; cvt.u32.u64 %0, t; }" : "=r"(a) : "l"(p));
    return a;
}
__device__ __forceinline__ void cp16(uint32_t dst, const float* src) {
    asm volatile("cp.async.cg.shared.global [%0], [%1], 16;" :: "r"(dst), "l"(src) : "memory");
}
__device__ __forceinline__ void mma_tf32(float* c, const uint32_t* a, const uint32_t* b) {
    asm volatile(
        "mma.sync.aligned.m16n8k8.row.col.f32.tf32.tf32.f32 "
        "{%0,%1,%2,%3}, {%4,%5,%6,%7}, {%8,%9}, {%0,%1,%2,%3};"
        : "+f"(c[0]), "+f"(c[1]), "+f"(c[2]), "+f"(c[3])
        : "r"(a[0]), "r"(a[1]), "r"(a[2]), "r"(a[3]), "r"(b[0]), "r"(b[1]));
}
__device__ __forceinline__ float sigmoidf_fast(float x) {
    return 1.f / (1.f + __expf(-x));
}
// m-permutation: m = wm*64+mf*16+h8*8+g  ->  wm*64+h8*32+g*4+mf
__device__ __forceinline__ int PI(int off) {
    return (off & 64) | ((off & 8) << 2) | ((off & 7) << 2) | ((off >> 4) & 3);
}
// n-permutation: n = wn*32+nf*8+g  ->  wn*32+g*4+nf
__device__ __forceinline__ int SIG(int off) {
    return (off & 96) | ((off & 7) << 2) | ((off >> 3) & 3);
}

// ---------------- pipelined GEMM mainloop (v4 fragment loads) ----------------
// Operand tiles in smem hold permuted data: A cols pi-permuted, B cols
// sig-permuted. Fragment loads read the v4 groups; permutations cancel so
// logical D row m = original m-index, D col n = original n-index.
__device__ __forceinline__ void gemm_mainloop(
    float c[4][4][4], float* smemf, uint32_t smemb,
    const float* aG, int strideA, const float* bG, int strideB,
    int tid, int wm, int wn, int g, int q)
{
    float* As = smemf;
    float* Bs = smemf + NSTG * TILE_FLOATS;
    const uint32_t aB = smemb;
    const uint32_t bB = smemb + NSTG * TILE_FLOATS * 4;

#pragma unroll
    for (int ch = 0; ch < 2; ch++) {
        const float* aGc = aG + (size_t)ch * BK * strideA;
        const float* bGc = bG + (size_t)ch * BK * strideB;
        const uint32_t aD = aB + ch * TILE_FLOATS * 4;
        const uint32_t bD = bB + ch * TILE_FLOATS * 4;
#pragma unroll
        for (int h = 0; h < 4; h++) {
            const int idx = tid + h * 256;
            const int row = idx >> 5, cc = idx & 31;
            cp16(aD + (row * LDA + cc * 4) * 4, aGc + (size_t)row * strideA + cc * 4);
            cp16(bD + (row * LDA + cc * 4) * 4, bGc + (size_t)row * strideB + cc * 4);
        }
        asm volatile("cp.async.commit_group;" ::: "memory");
    }

    for (int i = 0; i < NCHUNK; i++) {
        if (i + 1 < NCHUNK) asm volatile("cp.async.wait_group 1;" ::: "memory");
        else                asm volatile("cp.async.wait_group 0;" ::: "memory");
        __syncthreads();

        if (i + 2 < NCHUNK) {
            const int ch = i + 2, sl = ch % NSTG;
            const float* aGc = aG + (size_t)ch * BK * strideA;
            const float* bGc = bG + (size_t)ch * BK * strideB;
            const uint32_t aD = aB + sl * TILE_FLOATS * 4;
            const uint32_t bD = bB + sl * TILE_FLOATS * 4;
#pragma unroll
            for (int h = 0; h < 4; h++) {
                const int idx = tid + h * 256;
                const int row = idx >> 5, cc = idx & 31;
                cp16(aD + (row * LDA + cc * 4) * 4, aGc + (size_t)row * strideA + cc * 4);
                cp16(bD + (row * LDA + cc * 4) * 4, bGc + (size_t)row * strideB + cc * 4);
            }
            asm volatile("cp.async.commit_group;" ::: "memory");
        }

        const float* A = As + (i % NSTG) * TILE_FLOATS;
        const float* B = Bs + (i % NSTG) * TILE_FLOATS;
#pragma unroll
        for (int kc = 0; kc < BK; kc += 8) {
            const float4 A0 = *(const float4*)&A[(kc + q) * LDA + wm * 64 + g * 4];
            const float4 A1 = *(const float4*)&A[(kc + q) * LDA + wm * 64 + 32 + g * 4];
            const float4 A2 = *(const float4*)&A[(kc + q + 4) * LDA + wm * 64 + g * 4];
            const float4 A3 = *(const float4*)&A[(kc + q + 4) * LDA + wm * 64 + 32 + g * 4];
            const float4 B0 = *(const float4*)&B[(kc + q) * LDA + wn * 32 + g * 4];
            const float4 B1 = *(const float4*)&B[(kc + q + 4) * LDA + wn * 32 + g * 4];
            uint32_t a[4][4], bv[4][2];
            a[0][0] = __float_as_uint(A0.x); a[1][0] = __float_as_uint(A0.y);
            a[2][0] = __float_as_uint(A0.z); a[3][0] = __float_as_uint(A0.w);
            a[0][1] = __float_as_uint(A1.x); a[1][1] = __float_as_uint(A1.y);
            a[2][1] = __float_as_uint(A1.z); a[3][1] = __float_as_uint(A1.w);
            a[0][2] = __float_as_uint(A2.x); a[1][2] = __float_as_uint(A2.y);
            a[2][2] = __float_as_uint(A2.z); a[3][2] = __float_as_uint(A2.w);
            a[0][3] = __float_as_uint(A3.x); a[1][3] = __float_as_uint(A3.y);
            a[2][3] = __float_as_uint(A3.z); a[3][3] = __float_as_uint(A3.w);
            bv[0][0] = __float_as_uint(B0.x); bv[1][0] = __float_as_uint(B0.y);
            bv[2][0] = __float_as_uint(B0.z); bv[3][0] = __float_as_uint(B0.w);
            bv[0][1] = __float_as_uint(B1.x); bv[1][1] = __float_as_uint(B1.y);
            bv[2][1] = __float_as_uint(B1.z); bv[3][1] = __float_as_uint(B1.w);
#pragma unroll
            for (int mf = 0; mf < 4; mf++)
#pragma unroll
                for (int nf = 0; nf < 4; nf++) mma_tf32(c[mf][nf], a[mf], bv[nf]);
        }
    }
}

// ---------------- K0: Wsum ----------------------------------------------------
__global__ void k0_wsum(const float* __restrict__ W_out) {
    __shared__ float sm[256];
    const float* w = W_out + (size_t)(TT - 1) * TT;
    float acc = 0.f;
    for (int t = threadIdx.x; t < TT; t += 256) acc += w[t];
    sm[threadIdx.x] = acc;
    __syncthreads();
    for (int st = 128; st > 0; st >>= 1) {
        if (threadIdx.x < st) sm[threadIdx.x] += sm[threadIdx.x + st];
        __syncthreads();
    }
    if (threadIdx.x == 0) g_wsum = sm[0];
}

// ---------------- pre-passes: tf32-round + permute ---------------------------
__global__ void k_pXm(const float* __restrict__ xs) {
    const size_t i = (size_t)blockIdx.x * 256 + threadIdx.x;
    const int off = (int)(i & 127);
    g_Xm[(i & ~(size_t)127) + PI(off)] = to_tf32(xs[i]);
}
__global__ void k_pXn(const float* __restrict__ xs) {
    const size_t i = (size_t)blockIdx.x * 256 + threadIdx.x;
    const int off = (int)(i & 127);
    g_Xn[(i & ~(size_t)127) + SIG(off)] = to_tf32(xs[i]);
}
__global__ void k_pWn(const float* __restrict__ w) {
    const size_t i = (size_t)blockIdx.x * 256 + threadIdx.x;
    const int off = (int)(i & 127);
    g_Wn[(i & ~(size_t)127) + SIG(off)] = to_tf32(w[i]);
}

// ---------------- K1: q-tilde, writes Qt [b][d][pi(s)] -----------------------
__global__ __launch_bounds__(256, 2) void k1_qt() {
    extern __shared__ float smemf[];
    const uint32_t smemb = smem_u32(smemf);
    const int b  = blockIdx.z;
    const int s0 = blockIdx.x * 128;
    const int d0 = blockIdx.y * 128;
    const int tid = threadIdx.x;
    const int warp = tid >> 5, lane = tid & 31;
    const int wm = warp & 1, wn = warp >> 1;
    const int g = lane >> 2, q = lane & 3;
    const float sign = (blockIdx.y < 2) ? 1.f : -1.f;

    float c[4][4][4];
#pragma unroll
    for (int mf = 0; mf < 4; mf++)
#pragma unroll
        for (int nf = 0; nf < 4; nf++)
#pragma unroll
            for (int r = 0; r < 4; r++) c[mf][nf][r] = 0.f;

    gemm_mainloop(c, smemf, smemb,
                  g_Xm + (size_t)b * DD * TT + s0, TT,
                  g_Wn + d0, DD, tid, wm, wn, g, q);

    // D row m = orig s-off m; store at pi(m) so Qt is pi-stored like g_Xm.
    // pi(wm*64+mf*16+h8*8+g) = wm*64+h8*32+g*4+mf  -> mf contiguous: float4.
    float* qp = g_Qt + (size_t)b * DD * SS;
    const int sbase = s0 + wm * 64 + g * 4;
#pragma unroll
    for (int nf = 0; nf < 4; nf++) {
        const int d = d0 + wn * 32 + nf * 8 + 2 * q;
        float4 v;
        v.x = to_tf32(sign * c[0][nf][0]); v.y = to_tf32(sign * c[1][nf][0]);
        v.z = to_tf32(sign * c[2][nf][0]); v.w = to_tf32(sign * c[3][nf][0]);
        *(float4*)&qp[(size_t)d * SS + sbase] = v;
        v.x = to_tf32(sign * c[0][nf][1]); v.y = to_tf32(sign * c[1][nf][1]);
        v.z = to_tf32(sign * c[2][nf][1]); v.w = to_tf32(sign * c[3][nf][1]);
        *(float4*)&qp[(size_t)(d + 1) * SS + sbase] = v;
        v.x = to_tf32(sign * c[0][nf][2]); v.y = to_tf32(sign * c[1][nf][2]);
        v.z = to_tf32(sign * c[2][nf][2]); v.w = to_tf32(sign * c[3][nf][2]);
        *(float4*)&qp[(size_t)d * SS + sbase + 32] = v;
        v.x = to_tf32(sign * c[0][nf][3]); v.y = to_tf32(sign * c[1][nf][3]);
        v.z = to_tf32(sign * c[2][nf][3]); v.w = to_tf32(sign * c[3][nf][3]);
        *(float4*)&qp[(size_t)(d + 1) * SS + sbase + 32] = v;
    }
}

// ---------------- K2: Delta GEMM + fused sigmoid/weighted reduce -------------
__global__ __launch_bounds__(256, 2) void k2_attn(const float* __restrict__ W_out) {
    extern __shared__ float smemf[];
    __shared__ float red[4][129];
    const uint32_t smemb = smem_u32(smemf);
    const int b  = blockIdx.z;
    const int s0 = blockIdx.x * 128;
    const int t0 = blockIdx.y * 128;
    const int tid = threadIdx.x;
    const int warp = tid >> 5, lane = tid & 31;
    const int wm = warp & 1, wn = warp >> 1;
    const int g = lane >> 2, q = lane & 3;

    float c[4][4][4];
#pragma unroll
    for (int mf = 0; mf < 4; mf++)
#pragma unroll
        for (int nf = 0; nf < 4; nf++)
#pragma unroll
            for (int r = 0; r < 4; r++) c[mf][nf][r] = 0.f;

    // Qt is pi-stored (A), Xn is sig-stored (B): permutations cancel ->
    // D row m = orig s, D col n = orig t. Epilogue identical to unpermuted.
    gemm_mainloop(c, smemf, smemb,
                  g_Qt + (size_t)b * DD * SS + s0, SS,
                  g_Xn + (size_t)b * DD * TT + t0, TT, tid, wm, wn, g, q);

    const float* wrow = W_out + (size_t)(TT - 1) * TT + t0;
    float wv[4][2];
#pragma unroll
    for (int nf = 0; nf < 4; nf++) {
        const int col = wn * 32 + nf * 8 + 2 * q;
        wv[nf][0] = wrow[col];
        wv[nf][1] = wrow[col + 1];
    }
    float p[4][2];
#pragma unroll
    for (int mf = 0; mf < 4; mf++) { p[mf][0] = 0.f; p[mf][1] = 0.f; }
#pragma unroll
    for (int mf = 0; mf < 4; mf++)
#pragma unroll
        for (int nf = 0; nf < 4; nf++) {
            p[mf][0] += wv[nf][0] * sigmoidf_fast(c[mf][nf][0])
                      + wv[nf][1] * sigmoidf_fast(c[mf][nf][1]);
            p[mf][1] += wv[nf][0] * sigmoidf_fast(c[mf][nf][2])
                      + wv[nf][1] * sigmoidf_fast(c[mf][nf][3]);
        }
#pragma unroll
    for (int mf = 0; mf < 4; mf++)
#pragma unroll
        for (int r8 = 0; r8 < 2; r8++) {
            float v = p[mf][r8];
            v += __shfl_xor_sync(0xffffffffu, v, 1);
            v += __shfl_xor_sync(0xffffffffu, v, 2);
            p[mf][r8] = v;
        }
    __syncthreads();
    if (q == 0) {
#pragma unroll
        for (int mf = 0; mf < 4; mf++)
#pragma unroll
            for (int r8 = 0; r8 < 2; r8++)
                red[wn][wm * 64 + mf * 16 + r8 * 8 + g] = p[mf][r8];
    }
    __syncthreads();
    if (tid < 128) {
        const float acc = red[0][tid] + red[1][tid] + red[2][tid] + red[3][tid];
        g_gpart[((size_t)b * 16 + blockIdx.y) * SS + s0 + tid] = acc;
    }
}

// ---------------- K3: g0 = sum over t-tiles ----------------------------------
__global__ void k3_g0() {
    const int idx = blockIdx.x * 256 + threadIdx.x;
    const int b = idx >> 11;
    const float* pz = g_gpart + (size_t)b * 16 * SS + (idx & (SS - 1));
    float acc = 0.f;
#pragma unroll
    for (int tb = 0; tb < 16; tb++) acc += pz[(size_t)tb * SS];
    g_g0[idx] = acc;
}

// ---------------- K4: y0, rowsum (exact fp32 xs) -----------------------------
__global__ void k4_y(const float* __restrict__ xs) {
    const int d = blockIdx.x, b = blockIdx.y;
    const float* xr = xs + ((size_t)b * DD + d) * TT;
    const float* g = g_g0 + (size_t)b * SS;
    float ay = 0.f, ar = 0.f;
    for (int s = threadIdx.x; s < SVALID; s += 128) {
        const float x = xr[s];
        ay += x * g[s];
        ar += x;
    }
    __shared__ float sy[128], sr[128];
    sy[threadIdx.x] = ay; sr[threadIdx.x] = ar;
    __syncthreads();
    for (int st = 64; st > 0; st >>= 1) {
        if (threadIdx.x < st) {
            sy[threadIdx.x] += sy[threadIdx.x + st];
            sr[threadIdx.x] += sr[threadIdx.x + st];
        }
        __syncthreads();
    }
    if (threadIdx.x == 0) { g_y[b * DD + d] = sy[0]; g_r[b * DD + d] = sr[0]; }
}

// ---------------- K5: final W_PV contraction ---------------------------------
__global__ __launch_bounds__(512) void k5_out(const float* __restrict__ W_PV,
                                              float* __restrict__ out) {
    const int b = blockIdx.x;
    __shared__ float z0[DD], z1[DD];
    const float ws = g_wsum;
    {
        const int d = threadIdx.x;
        const float yv = g_y[b * DD + d];
        const float rv = g_r[b * DD + d];
        z0[d] = yv;
        z1[d] = ws * rv - yv;
    }
    __syncthreads();
    const int warp = threadIdx.x >> 5, lane = threadIdx.x & 31;
    for (int ii = 0; ii < 32; ii++) {
        const int i = warp * 32 + ii;
        const float* z = (i < 256) ? z0 : z1;
        const float* wp = W_PV + (size_t)i * DD;
        float acc = 0.f;
#pragma unroll
        for (int cix = 0; cix < 16; cix++) acc += wp[lane + cix * 32] * z[lane + cix * 32];
#pragma unroll
        for (int off = 16; off > 0; off >>= 1)
            acc += __shfl_down_sync(0xffffffffu, acc, off);
        if (lane == 0) out[b * DD + i] = acc;
    }
}

// ---------------- launch -----------------------------------------------------
extern "C" void kernel_launch(void* const* d_in, const int* in_sizes, int n_in,
                              void* d_out, int out_size) {
    const float* xs    = (const float*)d_in[0];
    const float* W_KQ  = (const float*)d_in[1];
    const float* W_PV  = (const float*)d_in[2];
    const float* W_out = (const float*)d_in[3];
    float* out = (float*)d_out;

    cudaFuncSetAttribute(k1_qt, cudaFuncAttributeMaxDynamicSharedMemorySize, SMEM_DYN);
    cudaFuncSetAttribute(k2_attn, cudaFuncAttributeMaxDynamicSharedMemorySize, SMEM_DYN);

    k0_wsum<<<1, 256>>>(W_out);
    k_pXm<<<(int)(((size_t)BB * DD * TT) / 256), 256>>>(xs);
    k_pXn<<<(int)(((size_t)BB * DD * TT) / 256), 256>>>(xs);
    k_pWn<<<(DD * DD) / 256, 256>>>(W_KQ);
    k1_qt<<<dim3(16, 4, BB), 256, SMEM_DYN>>>();
    k2_attn<<<dim3(16, 16, BB), 256, SMEM_DYN>>>(W_out);
    k3_g0<<<(BB * SS) / 256, 256>>>();
    k4_y<<<dim3(DD, BB), 128>>>(xs);
    k5_out<<<BB, 512>>>(W_PV, out);
}